// round 13
// baseline (speedup 1.0000x reference)
#include <cuda_runtime.h>
#include <cuda_fp16.h>
#include <math.h>
#include <stdint.h>

#define BATCH   4
#define SEQL    2048
#define DMODEL  1024
#define DINNER  2048
#define NST     16
#define LC      64
#define TCH     (SEQL / LC)     // 32
#define MTOT    (BATCH * SEQL)  // 8192

// ---------------- scratch (device globals) ----------------------------------
__device__ __align__(128) float  g_buf0 [MTOT * DINNER];   // silu'd ssm half (pre-conv) fp32
__device__ __align__(128) __half g_gateh[MTOT * DINNER];   // silu(x_res) fp16
__device__ __align__(128) __half g_xc16 [MTOT * DINNER];   // conv(x_ssm) fp16 [M][K]
__device__ __align__(128) float  g_B    [MTOT * NST];
__device__ __align__(128) float  g_C    [MTOT * NST];
__device__ __align__(128) float  g_hend [BATCH * TCH * DINNER * NST];
__device__ __align__(128) float  g_Hst  [BATCH * TCH * DINNER * NST];
__device__ __align__(128) __half g_xa   [MTOT * DMODEL];    // x fp16        [M][K]
__device__ __align__(128) __half g_ya   [MTOT * DINNER];    // y fp16        [M][K]
__device__ __align__(128) __half g_wint [4096 * 1024];      // W_in^T fp16   [N][K]
__device__ __align__(128) __half g_wot  [1024 * 2048];      // W_out^T fp16  [N][K]
__device__ __align__(128) __half g_wbc  [32 * DINNER];      // [W_B|W_C]^T fp16 [32][K]

__device__ __forceinline__ float siluf(float v) { return v / (1.0f + expf(-v)); }

// ---------------- PTX helpers ------------------------------------------------
__device__ __forceinline__ uint32_t smem_u32(const void* p) {
    uint32_t a;
    asm("{ .reg .u64 t; cvta.to.shared.u64 t, %1; cvt.u32.u64 %0, t; }" : "=r"(a) : "l"(p));
    return a;
}
__device__ __forceinline__ void cp16(uint32_t dst, const void* src) {
    asm volatile("cp.async.cg.shared.global [%0], [%1], 16;" :: "r"(dst), "l"(src) : "memory");
}
__device__ __forceinline__ void cp_commit() {
    asm volatile("cp.async.commit_group;" ::: "memory");
}
__device__ __forceinline__ void ldsm_x4(uint32_t* r, uint32_t addr) {
    asm volatile("ldmatrix.sync.aligned.m8n8.x4.shared.b16 {%0,%1,%2,%3}, [%4];"
        : "=r"(r[0]), "=r"(r[1]), "=r"(r[2]), "=r"(r[3]) : "r"(addr));
}
__device__ __forceinline__ void mma16816(float* d, const uint32_t* a, const uint32_t* b) {
    asm volatile(
        "mma.sync.aligned.m16n8k16.row.col.f32.f16.f16.f32 "
        "{%0,%1,%2,%3}, {%4,%5,%6,%7}, {%8,%9}, {%0,%1,%2,%3};"
        : "+f"(d[0]), "+f"(d[1]), "+f"(d[2]), "+f"(d[3])
        : "r"(a[0]), "r"(a[1]), "r"(a[2]), "r"(a[3]), "r"(b[0]), "r"(b[1]));
}
// packed fp32x2 (sm_100+ base feature)
__device__ __forceinline__ uint64_t pk2(float lo, float hi) {
    uint64_t r; asm("mov.b64 %0, {%1,%2};" : "=l"(r) : "f"(lo), "f"(hi)); return r;
}
__device__ __forceinline__ void upk2(uint64_t v, float& lo, float& hi) {
    asm("mov.b64 {%0,%1}, %2;" : "=f"(lo), "=f"(hi) : "l"(v));
}
__device__ __forceinline__ uint64_t fma2_(uint64_t a, uint64_t b, uint64_t c) {
    uint64_t d; asm("fma.rn.f32x2 %0, %1, %2, %3;" : "=l"(d) : "l"(a), "l"(b), "l"(c)); return d;
}
__device__ __forceinline__ uint64_t mul2_(uint64_t a, uint64_t b) {
    uint64_t d; asm("mul.rn.f32x2 %0, %1, %2;" : "=l"(d) : "l"(a), "l"(b)); return d;
}

// ---------------- HMMA fp16 GEMM (128x128) -------------------------------------
#define NSTAGE 3
#define STAGEB 16384
#define GSMEM  (NSTAGE * 2 * STAGEB)      // 96 KB

template<int K>
__device__ __forceinline__ void load_stage(uint32_t sb, const __half* Ag, const __half* Bg,
                                           int kt, int s, int r0, int c0) {
    const uint32_t abase = sb + s * (2 * STAGEB);
    const uint32_t bbase = abase + STAGEB;
    const __half* Ap = Ag + (size_t)kt * 64 + (size_t)r0 * K + c0 * 8;
    const __half* Bp = Bg + (size_t)kt * 64 + (size_t)r0 * K + c0 * 8;
    const uint32_t csw = (uint32_t)((c0 ^ (r0 & 7)) * 16);
#pragma unroll
    for (int p = 0; p < 4; p++) {
        const uint32_t off = (uint32_t)((r0 + p * 32) * 128) + csw;
        cp16(abase + off, Ap + (size_t)p * 32 * K);
        cp16(bbase + off, Bp + (size_t)p * 32 * K);
    }
}

template<int MODE, int N, int K>
__global__ void __launch_bounds__(256, 2) hgemm(const float* __restrict__ bias,
                                                float* __restrict__ out)
{
    extern __shared__ char smem[];
    const uint32_t sb = smem_u32(smem);
    const int tid = threadIdx.x, lane = tid & 31, wid = tid >> 5;
    const int bn = blockIdx.x, bm = blockIdx.y;

    const __half* Ag = (MODE == 0 ? g_xa : g_ya) + (size_t)bm * 128 * K;
    const __half* Bg = (MODE == 0 ? g_wint : g_wot) + (size_t)bn * 128 * K;
    const int r0 = tid >> 3, c0 = tid & 7;

#pragma unroll
    for (int s = 0; s < NSTAGE - 1; s++) { load_stage<K>(sb, Ag, Bg, s, s, r0, c0); cp_commit(); }

    const int wm0 = (wid & 1) * 64;
    const int wn0 = (wid >> 1) * 32;

    float acc[4][4][4];
#pragma unroll
    for (int mt = 0; mt < 4; mt++)
#pragma unroll
        for (int nt = 0; nt < 4; nt++)
#pragma unroll
            for (int q = 0; q < 4; q++) acc[mt][nt][q] = 0.0f;

    const int ar = lane & 15;
    const int ac = lane >> 4;
    const int br = lane & 7;
    const int bc = (lane >> 3) & 1;
    const int bq = lane >> 4;

    constexpr int KT = K / 64;
    int buf = 0;
    int wbuf = NSTAGE - 1;
    for (int kt = 0; kt < KT; kt++) {
        asm volatile("cp.async.wait_group %0;" :: "n"(NSTAGE - 2) : "memory");
        __syncthreads();

        const int next = kt + NSTAGE - 1;
        if (next < KT) load_stage<K>(sb, Ag, Bg, next, wbuf, r0, c0);
        cp_commit();
        wbuf++; if (wbuf == NSTAGE) wbuf = 0;

        const uint32_t abase = sb + buf * (2 * STAGEB);
        const uint32_t bbase = abase + STAGEB;
#pragma unroll
        for (int kk = 0; kk < 4; kk++) {
            uint32_t af[4][4], bf[4][2];
#pragma unroll
            for (int mt = 0; mt < 4; mt++) {
                const int row = wm0 + mt * 16 + ar;
                const int c = kk * 2 + ac;
                ldsm_x4(af[mt], abase + (uint32_t)(row * 128) + (uint32_t)((c ^ (row & 7)) << 4));
            }
#pragma unroll
            for (int np = 0; np < 2; np++) {
                const int row = wn0 + np * 16 + bq * 8 + br;
                const int c = kk * 2 + bc;
                uint32_t t[4];
                ldsm_x4(t, bbase + (uint32_t)(row * 128) + (uint32_t)((c ^ (row & 7)) << 4));
                bf[np * 2][0] = t[0]; bf[np * 2][1] = t[1];
                bf[np * 2 + 1][0] = t[2]; bf[np * 2 + 1][1] = t[3];
            }
#pragma unroll
            for (int mt = 0; mt < 4; mt++)
#pragma unroll
                for (int nt = 0; nt < 4; nt++)
                    mma16816(acc[mt][nt], af[mt], bf[nt]);
        }
        buf++; if (buf == NSTAGE) buf = 0;
    }

    // epilogue
    const int g = lane >> 2, t4 = lane & 3;
    float bb[8];
#pragma unroll
    for (int nt = 0; nt < 4; nt++) {
        bb[nt * 2]     = __ldg(bias + bn * 128 + wn0 + nt * 8 + t4 * 2);
        bb[nt * 2 + 1] = __ldg(bias + bn * 128 + wn0 + nt * 8 + t4 * 2 + 1);
    }
    if (MODE == 0) {
        constexpr int HALF = N / 2;
        const int gn = bn * 128;
        const bool isGate = (gn >= HALF);
        const int colb = (isGate ? gn - HALF : gn) + wn0;
#pragma unroll
        for (int mt = 0; mt < 4; mt++) {
            const int gr = bm * 128 + wm0 + mt * 16 + g;
#pragma unroll
            for (int nt = 0; nt < 4; nt++) {
                const int col = colb + nt * 8 + t4 * 2;
                const float v00 = siluf(acc[mt][nt][0] + bb[nt*2]), v01 = siluf(acc[mt][nt][1] + bb[nt*2+1]);
                const float v10 = siluf(acc[mt][nt][2] + bb[nt*2]), v11 = siluf(acc[mt][nt][3] + bb[nt*2+1]);
                if (!isGate) {
                    *(float2*)(g_buf0 + (size_t)gr * HALF + col)       = make_float2(v00, v01);
                    *(float2*)(g_buf0 + (size_t)(gr + 8) * HALF + col) = make_float2(v10, v11);
                } else {
                    *(__half2*)(g_gateh + (size_t)gr * HALF + col)       = __floats2half2_rn(v00, v01);
                    *(__half2*)(g_gateh + (size_t)(gr + 8) * HALF + col) = __floats2half2_rn(v10, v11);
                }
            }
        }
    } else {
#pragma unroll
        for (int mt = 0; mt < 4; mt++) {
            const int gr = bm * 128 + wm0 + mt * 16 + g;
#pragma unroll
            for (int nt = 0; nt < 4; nt++) {
                const int col = bn * 128 + wn0 + nt * 8 + t4 * 2;
                *(float2*)(out + (size_t)gr * N + col)       = make_float2(acc[mt][nt][0] + bb[nt*2], acc[mt][nt][1] + bb[nt*2+1]);
                *(float2*)(out + (size_t)(gr + 8) * N + col) = make_float2(acc[mt][nt][2] + bb[nt*2], acc[mt][nt][3] + bb[nt*2+1]);
            }
        }
    }
}

// ---------------- fused prep: everything independent of hgemm0 -------------------
template<int K, int N>
__device__ __forceinline__ void wtrans_tile(const float* __restrict__ W, __half* Wt,
                                            int bx, int by, int tid) {
    __shared__ float t[32][33];
    const int tx = tid & 31;
    const int ty = tid >> 5;
#pragma unroll
    for (int i = 0; i < 4; i++)
        t[ty + 8 * i][tx] = W[(size_t)(by * 32 + ty + 8 * i) * N + bx * 32 + tx];
    __syncthreads();
#pragma unroll
    for (int i = 0; i < 4; i++)
        Wt[(size_t)(bx * 32 + ty + 8 * i) * K + by * 32 + tx] = __float2half_rn(t[tx][ty + 8 * i]);
}

// blocks: [0,4096) convert_x (8/thread) | [4096,8192) wtrans W_in
//         [8192,10240) wtrans W_out | [10240,10304) wtrans_bc | [10304,10816) bc_init
__global__ __launch_bounds__(256) void prep(const float* __restrict__ x,
                                            const float* __restrict__ W_in,
                                            const float* __restrict__ W_out,
                                            const float* __restrict__ W_B,
                                            const float* __restrict__ W_C,
                                            const float* __restrict__ b_B,
                                            const float* __restrict__ B_mod,
                                            const float* __restrict__ b_C,
                                            const float* __restrict__ C_mod) {
    const int bid = blockIdx.x;
    if (bid < 4096) {
        const size_t i8 = ((size_t)bid * 256 + threadIdx.x) * 8;
        float v[8];
        *(float4*)&v[0] = *(const float4*)(x + i8);
        *(float4*)&v[4] = *(const float4*)(x + i8 + 4);
        uint4 o4;
        __half2* oh = (__half2*)&o4;
#pragma unroll
        for (int q = 0; q < 4; q++) oh[q] = __floats2half2_rn(v[q * 2], v[q * 2 + 1]);
        *(uint4*)(g_xa + i8) = o4;
    } else if (bid < 8192) {
        const int idx = bid - 4096;                 // 128 n x 32 k
        wtrans_tile<1024, 4096>(W_in, g_wint, idx & 127, idx >> 7, threadIdx.x);
    } else if (bid < 10240) {
        const int idx = bid - 8192;                 // 32 n x 64 k
        wtrans_tile<2048, 1024>(W_out, g_wot, idx & 31, idx >> 5, threadIdx.x);
    } else if (bid < 10304) {
        const int idx = ((bid - 10240) * 256 + threadIdx.x) * 4;  // over 32*2048
        const int n = idx >> 11;
        const int k = idx & 2047;
        const float* src = (n < 16) ? (W_B + n) : (W_C + n - 16);
#pragma unroll
        for (int q = 0; q < 4; q++)
            g_wbc[(size_t)n * DINNER + k + q] = __float2half_rn(src[(size_t)(k + q) * 16]);
    } else {
        const int i = (bid - 10304) * 256 + threadIdx.x;          // over MTOT*NST
        const int s = i & 15;
        const int b = i >> 15;
        g_B[i] = b_B[s] + B_mod[b * 16 + s];
        g_C[i] = b_C[s] + C_mod[b * 16 + s];
    }
}

// ---------------- depthwise conv(3) fp32 -> fp16, 8 elems/thread -----------------
__global__ __launch_bounds__(256) void conv16(const float* __restrict__ cw,
                                              const float* __restrict__ cb) {
    const size_t i8 = ((size_t)blockIdx.x * 256 + threadIdx.x) * 8;  // over MTOT*DINNER
    const int d0 = (int)(i8 & (DINNER - 1));
    const int l = (int)((i8 >> 11) & (SEQL - 1));

    float xc[8], xm[8], xp[8];
    *(float4*)&xc[0] = *(const float4*)(g_buf0 + i8);
    *(float4*)&xc[4] = *(const float4*)(g_buf0 + i8 + 4);
    if (l > 0) {
        *(float4*)&xm[0] = *(const float4*)(g_buf0 + i8 - DINNER);
        *(float4*)&xm[4] = *(const float4*)(g_buf0 + i8 - DINNER + 4);
    } else {
#pragma unroll
        for (int q = 0; q < 8; q++) xm[q] = 0.0f;
    }
    if (l < SEQL - 1) {
        *(float4*)&xp[0] = *(const float4*)(g_buf0 + i8 + DINNER);
        *(float4*)&xp[4] = *(const float4*)(g_buf0 + i8 + DINNER + 4);
    } else {
#pragma unroll
        for (int q = 0; q < 8; q++) xp[q] = 0.0f;
    }

    uint4 o4;
    __half2* oh = (__half2*)&o4;
#pragma unroll
    for (int q = 0; q < 4; q++) {
        const int d = d0 + q * 2;
        const float v0 = cw[d * 3 + 1] * xc[q*2]   + cw[d * 3 + 0] * xm[q*2]   + cw[d * 3 + 2] * xp[q*2]   + cb[d];
        const float v1 = cw[d * 3 + 4] * xc[q*2+1] + cw[d * 3 + 3] * xm[q*2+1] + cw[d * 3 + 5] * xp[q*2+1] + cb[d + 1];
        oh[q] = __floats2half2_rn(v0, v1);
    }
    *(uint4*)(g_xc16 + i8) = o4;
}

// ---------------- B/C projection: HMMA GEMM (N=32, K-split 4) --------------------
#define BC_ASTG 16384
#define BC_BSTG 4096
#define BC_SMEM (NSTAGE * (BC_ASTG + BC_BSTG))   // 61440

__global__ void __launch_bounds__(256, 2) bc_hmma()
{
    extern __shared__ char smem[];
    const uint32_t sb = smem_u32(smem);
    const int tid = threadIdx.x, lane = tid & 31, wid = tid >> 5;
    const int bm = blockIdx.x;
    const int ky = blockIdx.y;

    const __half* Ag = g_xc16 + (size_t)bm * 128 * DINNER + ky * 512;
    const __half* Bg = g_wbc + ky * 512;
    const int r0 = tid >> 3, c0 = tid & 7;
    const uint32_t csw = (uint32_t)((c0 ^ (r0 & 7)) * 16);

    auto load_bc = [&](int kt, int s) {
        const uint32_t abase = sb + s * BC_ASTG;
        const uint32_t bbase = sb + NSTAGE * BC_ASTG + s * BC_BSTG;
        const __half* Ap = Ag + (size_t)kt * 64 + (size_t)r0 * DINNER + c0 * 8;
#pragma unroll
        for (int p = 0; p < 4; p++)
            cp16(abase + (uint32_t)((r0 + p * 32) * 128) + csw, Ap + (size_t)p * 32 * DINNER);
        cp16(bbase + (uint32_t)(r0 * 128) + csw,
             Bg + (size_t)kt * 64 + (size_t)r0 * DINNER + c0 * 8);
    };

#pragma unroll
    for (int s = 0; s < NSTAGE - 1; s++) { load_bc(s, s); cp_commit(); }

    const int wm0 = wid * 16;
    float acc[4][4];
#pragma unroll
    for (int nt = 0; nt < 4; nt++)
#pragma unroll
        for (int q = 0; q < 4; q++) acc[nt][q] = 0.0f;

    const int ar = lane & 15;
    const int ac = lane >> 4;
    const int br = lane & 7;
    const int bc = (lane >> 3) & 1;
    const int bq = lane >> 4;

    constexpr int KT = 8;
    int buf = 0, wbuf = NSTAGE - 1;
    for (int kt = 0; kt < KT; kt++) {
        asm volatile("cp.async.wait_group %0;" :: "n"(NSTAGE - 2) : "memory");
        __syncthreads();

        const int next = kt + NSTAGE - 1;
        if (next < KT) load_bc(next, wbuf);
        cp_commit();
        wbuf++; if (wbuf == NSTAGE) wbuf = 0;

        const uint32_t abase = sb + buf * BC_ASTG;
        const uint32_t bbase = sb + NSTAGE * BC_ASTG + buf * BC_BSTG;
#pragma unroll
        for (int kk = 0; kk < 4; kk++) {
            uint32_t af[4], bf[4][2];
            {
                const int row = wm0 + ar;
                const int c = kk * 2 + ac;
                ldsm_x4(af, abase + (uint32_t)(row * 128) + (uint32_t)((c ^ (row & 7)) << 4));
            }
#pragma unroll
            for (int np = 0; np < 2; np++) {
                const int row = np * 16 + bq * 8 + br;
                const int c = kk * 2 + bc;
                uint32_t t[4];
                ldsm_x4(t, bbase + (uint32_t)(row * 128) + (uint32_t)((c ^ (row & 7)) << 4));
                bf[np * 2][0] = t[0]; bf[np * 2][1] = t[1];
                bf[np * 2 + 1][0] = t[2]; bf[np * 2 + 1][1] = t[3];
            }
#pragma unroll
            for (int nt = 0; nt < 4; nt++)
                mma16816(acc[nt], af, bf[nt]);
        }
        buf++; if (buf == NSTAGE) buf = 0;
    }

    const int g = lane >> 2, t4 = lane & 3;
#pragma unroll
    for (int nt = 0; nt < 4; nt++) {
        const int col0 = nt * 8 + t4 * 2;
#pragma unroll
        for (int rr = 0; rr < 2; rr++) {
            const int row = bm * 128 + wm0 + g + rr * 8;
            const float v0 = acc[nt][rr * 2], v1 = acc[nt][rr * 2 + 1];
#pragma unroll
            for (int q = 0; q < 2; q++) {
                const int col = col0 + q;
                const float v = q ? v1 : v0;
                if (col < 16) atomicAdd(&g_B[(size_t)row * 16 + col], v);
                else          atomicAdd(&g_C[(size_t)row * 16 + col - 16], v);
            }
        }
    }
}

// ---------------- scan pass 1: per-chunk end state (f32x2 math) -----------------
__global__ __launch_bounds__(256) void scan_pass1(const float* __restrict__ A_log)
{
    const int tid = threadIdx.x;
    const int d = blockIdx.x * 256 + tid;
    const int c = blockIdx.y;
    const int b = blockIdx.z;

    __shared__ float Bsh[LC * NST];
    {
        const float4* src = (const float4*)(g_B + (size_t)(b * SEQL + c * LC) * NST);
        ((float4*)Bsh)[tid] = src[tid];
    }

    uint64_t abar2[8];
#pragma unroll
    for (int p = 0; p < 8; p++) {
        const float a0 = expf(-expf(A_log[d * NST + 2 * p])     * 0.1f);
        const float a1 = expf(-expf(A_log[d * NST + 2 * p + 1]) * 0.1f);
        abar2[p] = pk2(a0, a1);
    }

    __syncthreads();

    uint64_t h2[8];
#pragma unroll
    for (int p = 0; p < 8; p++) h2[p] = 0ull;

    const __half* xp = g_xc16 + (size_t)(b * SEQL + c * LC) * DINNER + d;
#pragma unroll 4
    for (int k = 0; k < LC; k++) {
        const float x = __half2float(xp[(size_t)k * DINNER]);
        const uint64_t xx2 = pk2(x, x);
#pragma unroll
        for (int p = 0; p < 8; p++) {
            const uint64_t Bv = *(const uint64_t*)&Bsh[k * NST + 2 * p];
            h2[p] = fma2_(abar2[p], h2[p], mul2_(xx2, Bv));
        }
    }

    uint64_t* hp = (uint64_t*)(g_hend + ((((size_t)(b * TCH + c)) * DINNER + d) << 4));
#pragma unroll
    for (int p = 0; p < 8; p++) hp[p] = h2[p];
}

// ---------------- scan pass 2: cross-chunk scan (2 states/thread, f32x2) --------
__global__ __launch_bounds__(256) void scan_pass2(const float* __restrict__ A_log)
{
    const int gid = blockIdx.x * 256 + threadIdx.x;   // over BATCH*DINNER*8
    const int p = gid & 7;
    const int d = (gid >> 3) & (DINNER - 1);
    const int b = gid >> 14;

    const float a0 = expf(-expf(A_log[d * NST + 2 * p])     * 0.1f * (float)LC);
    const float a1 = expf(-expf(A_log[d * NST + 2 * p + 1]) * 0.1f * (float)LC);
    const uint64_t ap2 = pk2(a0, a1);

    uint64_t H = 0ull;
#pragma unroll 8
    for (int c = 0; c < TCH; c++) {
        const size_t idx = ((((size_t)(b * TCH + c)) * DINNER + d) << 4) + 2 * p;
        *(uint64_t*)(g_Hst + idx) = H;
        H = fma2_(ap2, H, *(const uint64_t*)(g_hend + idx));
    }
}

// ---------------- scan pass 3: local scan + y + D*x + gate (f32x2 math) --------
__global__ __launch_bounds__(256) void scan_pass3(const float* __restrict__ A_log,
                                                  const float* __restrict__ Dvec)
{
    const int tid = threadIdx.x;
    const int d = blockIdx.x * 256 + tid;
    const int c = blockIdx.y;
    const int b = blockIdx.z;

    __shared__ float Bsh[LC * NST];
    __shared__ float Csh[LC * NST];
    {
        const size_t base = (size_t)(b * SEQL + c * LC) * NST;
        ((float4*)Bsh)[tid] = ((const float4*)(g_B + base))[tid];
        ((float4*)Csh)[tid] = ((const float4*)(g_C + base))[tid];
    }

    uint64_t abar2[8];
#pragma unroll
    for (int p = 0; p < 8; p++) {
        const float a0 = expf(-expf(A_log[d * NST + 2 * p])     * 0.1f);
        const float a1 = expf(-expf(A_log[d * NST + 2 * p + 1]) * 0.1f);
        abar2[p] = pk2(a0, a1);
    }
    const float Dd = Dvec[d];

    uint64_t h2[8];
    {
        const uint64_t* Hp = (const uint64_t*)(g_Hst + ((((size_t)(b * TCH + c)) * DINNER + d) << 4));
#pragma unroll
        for (int p = 0; p < 8; p++) h2[p] = Hp[p];
    }

    __syncthreads();

    const size_t off = (size_t)(b * SEQL + c * LC) * DINNER + d;
    const __half* xp = g_xc16 + off;
    const __half* gp = g_gateh + off;
    __half* yp = g_ya + off;

#pragma unroll 4
    for (int k = 0; k < LC; k++) {
        const float x = __half2float(xp[(size_t)k * DINNER]);
        const uint64_t xx2 = pk2(x, x);
        uint64_t acc2 = 0ull;
#pragma unroll
        for (int p = 0; p < 8; p++) {
            const uint64_t Bv = *(const uint64_t*)&Bsh[k * NST + 2 * p];
            h2[p] = fma2_(abar2[p], h2[p], mul2_(xx2, Bv));
            const uint64_t Cv = *(const uint64_t*)&Csh[k * NST + 2 * p];
            acc2 = fma2_(Cv, h2[p], acc2);
        }
        float alo, ahi; upk2(acc2, alo, ahi);
        const float y = (alo + ahi + Dd * x) * __half2float(gp[(size_t)k * DINNER]);
        yp[(size_t)k * DINNER] = __float2half_rn(y);
    }
}

// ---------------- launch ---------------------------------------------------------
extern "C" void kernel_launch(void* const* d_in, const int* in_sizes, int n_in,
                              void* d_out, int out_size)
{
    const float* x      = (const float*)d_in[0];
    const float* B_mod  = (const float*)d_in[1];
    const float* C_mod  = (const float*)d_in[2];
    const float* W_in   = (const float*)d_in[3];
    const float* b_in   = (const float*)d_in[4];
    const float* conv_w = (const float*)d_in[5];
    const float* conv_b = (const float*)d_in[6];
    const float* A_log  = (const float*)d_in[7];
    const float* Dv     = (const float*)d_in[8];
    const float* W_B    = (const float*)d_in[9];
    const float* b_B    = (const float*)d_in[10];
    const float* W_C    = (const float*)d_in[11];
    const float* b_C    = (const float*)d_in[12];
    const float* W_out  = (const float*)d_in[13];
    const float* b_out  = (const float*)d_in[14];
    float* out = (float*)d_out;

    cudaFuncSetAttribute(hgemm<0, 4096, 1024>,
                         cudaFuncAttributeMaxDynamicSharedMemorySize, GSMEM);
    cudaFuncSetAttribute(hgemm<1, 1024, 2048>,
                         cudaFuncAttributeMaxDynamicSharedMemorySize, GSMEM);
    cudaFuncSetAttribute(bc_hmma,
                         cudaFuncAttributeMaxDynamicSharedMemorySize, BC_SMEM);

    // 0) fused prep (convert x, transpose W_in/W_out/W_BC, init g_B/g_C biases)
    prep<<<10816, 256>>>(x, W_in, W_out, W_B, W_C, b_B, B_mod, b_C, C_mod);

    // 1) in_proj (HMMA fp16) + split + silu (x half fp32, gate fp16)
    hgemm<0, 4096, 1024><<<dim3(4096 / 128, MTOT / 128), 256, GSMEM>>>(b_in, nullptr);

    // 2) depthwise conv fp32->fp16 (8/thread), then B/C projections (HMMA)
    conv16<<<(MTOT * DINNER / 8) / 256, 256>>>(conv_w, conv_b);
    bc_hmma<<<dim3(MTOT / 128, 4), 256, BC_SMEM>>>();

    // 3) chunked scan (x from fp16 conv buffer; f32x2 packed state math)
    scan_pass1<<<dim3(DINNER / 256, TCH, BATCH), 256>>>(A_log);
    scan_pass2<<<(BATCH * DINNER * 8) / 256, 256>>>(A_log);
    scan_pass3<<<dim3(DINNER / 256, TCH, BATCH), 256>>>(A_log, Dv);

    // 4) out_proj (HMMA fp16)
    hgemm<1, 1024, 2048><<<dim3(1024 / 128, MTOT / 128), 256, GSMEM>>>(b_out, out);
}

// round 14
// speedup vs baseline: 1.0635x; 1.0635x over previous
#include <cuda_runtime.h>
#include <cuda_fp16.h>
#include <math.h>
#include <stdint.h>

#define BATCH   4
#define SEQL    2048
#define DMODEL  1024
#define DINNER  2048
#define NST     16
#define LC      64
#define TCH     (SEQL / LC)     // 32
#define MTOT    (BATCH * SEQL)  // 8192

// ---------------- scratch (device globals) ----------------------------------
__device__ __align__(128) float  g_buf0 [MTOT * DINNER];   // silu'd ssm half (pre-conv) fp32
__device__ __align__(128) __half g_gateh[MTOT * DINNER];   // silu(x_res) fp16
__device__ __align__(128) __half g_xc16 [MTOT * DINNER];   // conv(x_ssm) fp16 [M][K]
__device__ __align__(128) float  g_B    [MTOT * NST];
__device__ __align__(128) float  g_C    [MTOT * NST];
__device__ __align__(128) float  g_hend [BATCH * TCH * DINNER * NST];
__device__ __align__(128) float  g_Hst  [BATCH * TCH * DINNER * NST];
__device__ __align__(128) __half g_xa   [MTOT * DMODEL];    // x fp16        [M][K]
__device__ __align__(128) __half g_ya   [MTOT * DINNER];    // y fp16        [M][K]
__device__ __align__(128) __half g_wint [4096 * 1024];      // W_in^T fp16   [N][K]
__device__ __align__(128) __half g_wot  [1024 * 2048];      // W_out^T fp16  [N][K]
__device__ __align__(128) __half g_wbc  [32 * DINNER];      // [W_B|W_C]^T fp16 [32][K]

__device__ __forceinline__ float siluf(float v) { return v / (1.0f + expf(-v)); }

// ---------------- PTX helpers ------------------------------------------------
__device__ __forceinline__ uint32_t smem_u32(const void* p) {
    uint32_t a;
    asm("{ .reg .u64 t; cvta.to.shared.u64 t, %1; cvt.u32.u64 %0, t; }" : "=r"(a) : "l"(p));
    return a;
}
__device__ __forceinline__ void cp16(uint32_t dst, const void* src) {
    asm volatile("cp.async.cg.shared.global [%0], [%1], 16;" :: "r"(dst), "l"(src) : "memory");
}
__device__ __forceinline__ void cp_commit() {
    asm volatile("cp.async.commit_group;" ::: "memory");
}
__device__ __forceinline__ void ldsm_x4(uint32_t* r, uint32_t addr) {
    asm volatile("ldmatrix.sync.aligned.m8n8.x4.shared.b16 {%0,%1,%2,%3}, [%4];"
        : "=r"(r[0]), "=r"(r[1]), "=r"(r[2]), "=r"(r[3]) : "r"(addr));
}
__device__ __forceinline__ void mma16816(float* d, const uint32_t* a, const uint32_t* b) {
    asm volatile(
        "mma.sync.aligned.m16n8k16.row.col.f32.f16.f16.f32 "
        "{%0,%1,%2,%3}, {%4,%5,%6,%7}, {%8,%9}, {%0,%1,%2,%3};"
        : "+f"(d[0]), "+f"(d[1]), "+f"(d[2]), "+f"(d[3])
        : "r"(a[0]), "r"(a[1]), "r"(a[2]), "r"(a[3]), "r"(b[0]), "r"(b[1]));
}
// packed fp32x2 (sm_100+ base feature)
__device__ __forceinline__ uint64_t pk2(float lo, float hi) {
    uint64_t r; asm("mov.b64 %0, {%1,%2};" : "=l"(r) : "f"(lo), "f"(hi)); return r;
}
__device__ __forceinline__ void upk2(uint64_t v, float& lo, float& hi) {
    asm("mov.b64 {%0,%1}, %2;" : "=f"(lo), "=f"(hi) : "l"(v));
}
__device__ __forceinline__ uint64_t fma2_(uint64_t a, uint64_t b, uint64_t c) {
    uint64_t d; asm("fma.rn.f32x2 %0, %1, %2, %3;" : "=l"(d) : "l"(a), "l"(b), "l"(c)); return d;
}
__device__ __forceinline__ uint64_t mul2_(uint64_t a, uint64_t b) {
    uint64_t d; asm("mul.rn.f32x2 %0, %1, %2;" : "=l"(d) : "l"(a), "l"(b)); return d;
}

// ---------------- HMMA fp16 GEMM (128x128) -------------------------------------
#define NSTAGE 3
#define STAGEB 16384
#define GSMEM  (NSTAGE * 2 * STAGEB)      // 96 KB

template<int K>
__device__ __forceinline__ void load_stage(uint32_t sb, const __half* Ag, const __half* Bg,
                                           int kt, int s, int r0, int c0) {
    const uint32_t abase = sb + s * (2 * STAGEB);
    const uint32_t bbase = abase + STAGEB;
    const __half* Ap = Ag + (size_t)kt * 64 + (size_t)r0 * K + c0 * 8;
    const __half* Bp = Bg + (size_t)kt * 64 + (size_t)r0 * K + c0 * 8;
    const uint32_t csw = (uint32_t)((c0 ^ (r0 & 7)) * 16);
#pragma unroll
    for (int p = 0; p < 4; p++) {
        const uint32_t off = (uint32_t)((r0 + p * 32) * 128) + csw;
        cp16(abase + off, Ap + (size_t)p * 32 * K);
        cp16(bbase + off, Bp + (size_t)p * 32 * K);
    }
}

template<int MODE, int N, int K>
__global__ void __launch_bounds__(256, 2) hgemm(const float* __restrict__ bias,
                                                float* __restrict__ out)
{
    extern __shared__ char smem[];
    const uint32_t sb = smem_u32(smem);
    const int tid = threadIdx.x, lane = tid & 31, wid = tid >> 5;
    const int bn = blockIdx.x, bm = blockIdx.y;

    const __half* Ag = (MODE == 0 ? g_xa : g_ya) + (size_t)bm * 128 * K;
    const __half* Bg = (MODE == 0 ? g_wint : g_wot) + (size_t)bn * 128 * K;
    const int r0 = tid >> 3, c0 = tid & 7;

#pragma unroll
    for (int s = 0; s < NSTAGE - 1; s++) { load_stage<K>(sb, Ag, Bg, s, s, r0, c0); cp_commit(); }

    const int wm0 = (wid & 1) * 64;
    const int wn0 = (wid >> 1) * 32;

    float acc[4][4][4];
#pragma unroll
    for (int mt = 0; mt < 4; mt++)
#pragma unroll
        for (int nt = 0; nt < 4; nt++)
#pragma unroll
            for (int q = 0; q < 4; q++) acc[mt][nt][q] = 0.0f;

    const int ar = lane & 15;
    const int ac = lane >> 4;
    const int br = lane & 7;
    const int bc = (lane >> 3) & 1;
    const int bq = lane >> 4;

    constexpr int KT = K / 64;
    int buf = 0;
    int wbuf = NSTAGE - 1;
    for (int kt = 0; kt < KT; kt++) {
        asm volatile("cp.async.wait_group %0;" :: "n"(NSTAGE - 2) : "memory");
        __syncthreads();

        const int next = kt + NSTAGE - 1;
        if (next < KT) load_stage<K>(sb, Ag, Bg, next, wbuf, r0, c0);
        cp_commit();
        wbuf++; if (wbuf == NSTAGE) wbuf = 0;

        const uint32_t abase = sb + buf * (2 * STAGEB);
        const uint32_t bbase = abase + STAGEB;
#pragma unroll
        for (int kk = 0; kk < 4; kk++) {
            uint32_t af[4][4], bf[4][2];
#pragma unroll
            for (int mt = 0; mt < 4; mt++) {
                const int row = wm0 + mt * 16 + ar;
                const int c = kk * 2 + ac;
                ldsm_x4(af[mt], abase + (uint32_t)(row * 128) + (uint32_t)((c ^ (row & 7)) << 4));
            }
#pragma unroll
            for (int np = 0; np < 2; np++) {
                const int row = wn0 + np * 16 + bq * 8 + br;
                const int c = kk * 2 + bc;
                uint32_t t[4];
                ldsm_x4(t, bbase + (uint32_t)(row * 128) + (uint32_t)((c ^ (row & 7)) << 4));
                bf[np * 2][0] = t[0]; bf[np * 2][1] = t[1];
                bf[np * 2 + 1][0] = t[2]; bf[np * 2 + 1][1] = t[3];
            }
#pragma unroll
            for (int mt = 0; mt < 4; mt++)
#pragma unroll
                for (int nt = 0; nt < 4; nt++)
                    mma16816(acc[mt][nt], af[mt], bf[nt]);
        }
        buf++; if (buf == NSTAGE) buf = 0;
    }

    // epilogue
    const int g = lane >> 2, t4 = lane & 3;
    float bb[8];
#pragma unroll
    for (int nt = 0; nt < 4; nt++) {
        bb[nt * 2]     = __ldg(bias + bn * 128 + wn0 + nt * 8 + t4 * 2);
        bb[nt * 2 + 1] = __ldg(bias + bn * 128 + wn0 + nt * 8 + t4 * 2 + 1);
    }
    if (MODE == 0) {
        constexpr int HALF = N / 2;
        const int gn = bn * 128;
        const bool isGate = (gn >= HALF);
        const int colb = (isGate ? gn - HALF : gn) + wn0;
#pragma unroll
        for (int mt = 0; mt < 4; mt++) {
            const int gr = bm * 128 + wm0 + mt * 16 + g;
#pragma unroll
            for (int nt = 0; nt < 4; nt++) {
                const int col = colb + nt * 8 + t4 * 2;
                const float v00 = siluf(acc[mt][nt][0] + bb[nt*2]), v01 = siluf(acc[mt][nt][1] + bb[nt*2+1]);
                const float v10 = siluf(acc[mt][nt][2] + bb[nt*2]), v11 = siluf(acc[mt][nt][3] + bb[nt*2+1]);
                if (!isGate) {
                    *(float2*)(g_buf0 + (size_t)gr * HALF + col)       = make_float2(v00, v01);
                    *(float2*)(g_buf0 + (size_t)(gr + 8) * HALF + col) = make_float2(v10, v11);
                } else {
                    *(__half2*)(g_gateh + (size_t)gr * HALF + col)       = __floats2half2_rn(v00, v01);
                    *(__half2*)(g_gateh + (size_t)(gr + 8) * HALF + col) = __floats2half2_rn(v10, v11);
                }
            }
        }
    } else {
#pragma unroll
        for (int mt = 0; mt < 4; mt++) {
            const int gr = bm * 128 + wm0 + mt * 16 + g;
#pragma unroll
            for (int nt = 0; nt < 4; nt++) {
                const int col = bn * 128 + wn0 + nt * 8 + t4 * 2;
                *(float2*)(out + (size_t)gr * N + col)       = make_float2(acc[mt][nt][0] + bb[nt*2], acc[mt][nt][1] + bb[nt*2+1]);
                *(float2*)(out + (size_t)(gr + 8) * N + col) = make_float2(acc[mt][nt][2] + bb[nt*2], acc[mt][nt][3] + bb[nt*2+1]);
            }
        }
    }
}

// ---------------- fused prep: everything independent of hgemm0 -------------------
template<int K, int N>
__device__ __forceinline__ void wtrans_tile(const float* __restrict__ W, __half* Wt,
                                            int bx, int by, int tid) {
    __shared__ float t[32][33];
    const int tx = tid & 31;
    const int ty = tid >> 5;
#pragma unroll
    for (int i = 0; i < 4; i++)
        t[ty + 8 * i][tx] = W[(size_t)(by * 32 + ty + 8 * i) * N + bx * 32 + tx];
    __syncthreads();
#pragma unroll
    for (int i = 0; i < 4; i++)
        Wt[(size_t)(bx * 32 + ty + 8 * i) * K + by * 32 + tx] = __float2half_rn(t[tx][ty + 8 * i]);
}

// blocks: [0,8192) convert_x | [8192,12288) wtrans W_in | [12288,14336) wtrans W_out
//         [14336,14400) wtrans_bc | [14400,14912) bc_init
__global__ __launch_bounds__(256) void prep(const float* __restrict__ x,
                                            const float* __restrict__ W_in,
                                            const float* __restrict__ W_out,
                                            const float* __restrict__ W_B,
                                            const float* __restrict__ W_C,
                                            const float* __restrict__ b_B,
                                            const float* __restrict__ B_mod,
                                            const float* __restrict__ b_C,
                                            const float* __restrict__ C_mod) {
    const int bid = blockIdx.x;
    if (bid < 8192) {
        const int i = bid * 256 + threadIdx.x;
        const float4 v = ((const float4*)x)[i];
        __half2* o = (__half2*)g_xa;
        o[i * 2]     = __floats2half2_rn(v.x, v.y);
        o[i * 2 + 1] = __floats2half2_rn(v.z, v.w);
    } else if (bid < 12288) {
        const int idx = bid - 8192;                 // 128 n x 32 k
        wtrans_tile<1024, 4096>(W_in, g_wint, idx & 127, idx >> 7, threadIdx.x);
    } else if (bid < 14336) {
        const int idx = bid - 12288;                // 32 n x 64 k
        wtrans_tile<2048, 1024>(W_out, g_wot, idx & 31, idx >> 5, threadIdx.x);
    } else if (bid < 14400) {
        const int idx = ((bid - 14336) * 256 + threadIdx.x) * 4;  // over 32*2048
        const int n = idx >> 11;
        const int k = idx & 2047;
        const float* src = (n < 16) ? (W_B + n) : (W_C + n - 16);
#pragma unroll
        for (int q = 0; q < 4; q++)
            g_wbc[(size_t)n * DINNER + k + q] = __float2half_rn(src[(size_t)(k + q) * 16]);
    } else {
        const int i = (bid - 14400) * 256 + threadIdx.x;          // over MTOT*NST
        const int s = i & 15;
        const int b = i >> 15;
        g_B[i] = b_B[s] + B_mod[b * 16 + s];
        g_C[i] = b_C[s] + C_mod[b * 16 + s];
    }
}

// ---------------- depthwise conv(3) fp32 -> fp16 ---------------------------------
__global__ __launch_bounds__(256) void conv16(const float* __restrict__ cw,
                                              const float* __restrict__ cb) {
    const size_t i2 = (size_t)blockIdx.x * 256 + threadIdx.x;   // over MTOT*DINNER/2
    const size_t i = i2 * 2;
    const int d = (int)(i & (DINNER - 1));
    const int l = (int)((i >> 11) & (SEQL - 1));
    const float2 xc = *(const float2*)(g_buf0 + i);
    float v0 = cw[d * 3 + 1]     * xc.x + cb[d];
    float v1 = cw[d * 3 + 4]     * xc.y + cb[d + 1];
    if (l > 0) {
        const float2 xm = *(const float2*)(g_buf0 + i - DINNER);
        v0 += cw[d * 3 + 0] * xm.x;
        v1 += cw[d * 3 + 3] * xm.y;
    }
    if (l < SEQL - 1) {
        const float2 xp = *(const float2*)(g_buf0 + i + DINNER);
        v0 += cw[d * 3 + 2] * xp.x;
        v1 += cw[d * 3 + 5] * xp.y;
    }
    ((__half2*)g_xc16)[i2] = __floats2half2_rn(v0, v1);
}

// ---------------- B/C projection: HMMA GEMM (N=32, K-split 4) --------------------
#define BC_ASTG 16384
#define BC_BSTG 4096
#define BC_SMEM (NSTAGE * (BC_ASTG + BC_BSTG))   // 61440

__global__ void __launch_bounds__(256, 2) bc_hmma()
{
    extern __shared__ char smem[];
    const uint32_t sb = smem_u32(smem);
    const int tid = threadIdx.x, lane = tid & 31, wid = tid >> 5;
    const int bm = blockIdx.x;
    const int ky = blockIdx.y;

    const __half* Ag = g_xc16 + (size_t)bm * 128 * DINNER + ky * 512;
    const __half* Bg = g_wbc + ky * 512;
    const int r0 = tid >> 3, c0 = tid & 7;
    const uint32_t csw = (uint32_t)((c0 ^ (r0 & 7)) * 16);

    auto load_bc = [&](int kt, int s) {
        const uint32_t abase = sb + s * BC_ASTG;
        const uint32_t bbase = sb + NSTAGE * BC_ASTG + s * BC_BSTG;
        const __half* Ap = Ag + (size_t)kt * 64 + (size_t)r0 * DINNER + c0 * 8;
#pragma unroll
        for (int p = 0; p < 4; p++)
            cp16(abase + (uint32_t)((r0 + p * 32) * 128) + csw, Ap + (size_t)p * 32 * DINNER);
        cp16(bbase + (uint32_t)(r0 * 128) + csw,
             Bg + (size_t)kt * 64 + (size_t)r0 * DINNER + c0 * 8);
    };

#pragma unroll
    for (int s = 0; s < NSTAGE - 1; s++) { load_bc(s, s); cp_commit(); }

    const int wm0 = wid * 16;
    float acc[4][4];
#pragma unroll
    for (int nt = 0; nt < 4; nt++)
#pragma unroll
        for (int q = 0; q < 4; q++) acc[nt][q] = 0.0f;

    const int ar = lane & 15;
    const int ac = lane >> 4;
    const int br = lane & 7;
    const int bc = (lane >> 3) & 1;
    const int bq = lane >> 4;

    constexpr int KT = 8;
    int buf = 0, wbuf = NSTAGE - 1;
    for (int kt = 0; kt < KT; kt++) {
        asm volatile("cp.async.wait_group %0;" :: "n"(NSTAGE - 2) : "memory");
        __syncthreads();

        const int next = kt + NSTAGE - 1;
        if (next < KT) load_bc(next, wbuf);
        cp_commit();
        wbuf++; if (wbuf == NSTAGE) wbuf = 0;

        const uint32_t abase = sb + buf * BC_ASTG;
        const uint32_t bbase = sb + NSTAGE * BC_ASTG + buf * BC_BSTG;
#pragma unroll
        for (int kk = 0; kk < 4; kk++) {
            uint32_t af[4], bf[4][2];
            {
                const int row = wm0 + ar;
                const int c = kk * 2 + ac;
                ldsm_x4(af, abase + (uint32_t)(row * 128) + (uint32_t)((c ^ (row & 7)) << 4));
            }
#pragma unroll
            for (int np = 0; np < 2; np++) {
                const int row = np * 16 + bq * 8 + br;
                const int c = kk * 2 + bc;
                uint32_t t[4];
                ldsm_x4(t, bbase + (uint32_t)(row * 128) + (uint32_t)((c ^ (row & 7)) << 4));
                bf[np * 2][0] = t[0]; bf[np * 2][1] = t[1];
                bf[np * 2 + 1][0] = t[2]; bf[np * 2 + 1][1] = t[3];
            }
#pragma unroll
            for (int nt = 0; nt < 4; nt++)
                mma16816(acc[nt], af, bf[nt]);
        }
        buf++; if (buf == NSTAGE) buf = 0;
    }

    const int g = lane >> 2, t4 = lane & 3;
#pragma unroll
    for (int nt = 0; nt < 4; nt++) {
        const int col0 = nt * 8 + t4 * 2;
#pragma unroll
        for (int rr = 0; rr < 2; rr++) {
            const int row = bm * 128 + wm0 + g + rr * 8;
            const float v0 = acc[nt][rr * 2], v1 = acc[nt][rr * 2 + 1];
#pragma unroll
            for (int q = 0; q < 2; q++) {
                const int col = col0 + q;
                const float v = q ? v1 : v0;
                if (col < 16) atomicAdd(&g_B[(size_t)row * 16 + col], v);
                else          atomicAdd(&g_C[(size_t)row * 16 + col - 16], v);
            }
        }
    }
}

// ---------------- scan pass 1: per-chunk end state (f32x2 math) -----------------
__global__ __launch_bounds__(256) void scan_pass1(const float* __restrict__ A_log)
{
    const int tid = threadIdx.x;
    const int d = blockIdx.x * 256 + tid;
    const int c = blockIdx.y;
    const int b = blockIdx.z;

    __shared__ float Bsh[LC * NST];
    {
        const float4* src = (const float4*)(g_B + (size_t)(b * SEQL + c * LC) * NST);
        ((float4*)Bsh)[tid] = src[tid];
    }

    uint64_t abar2[8];
#pragma unroll
    for (int p = 0; p < 8; p++) {
        const float a0 = expf(-expf(A_log[d * NST + 2 * p])     * 0.1f);
        const float a1 = expf(-expf(A_log[d * NST + 2 * p + 1]) * 0.1f);
        abar2[p] = pk2(a0, a1);
    }

    __syncthreads();

    uint64_t h2[8];
#pragma unroll
    for (int p = 0; p < 8; p++) h2[p] = 0ull;

    const __half* xp = g_xc16 + (size_t)(b * SEQL + c * LC) * DINNER + d;
#pragma unroll 4
    for (int k = 0; k < LC; k++) {
        const float x = __half2float(xp[(size_t)k * DINNER]);
        const uint64_t xx2 = pk2(x, x);
#pragma unroll
        for (int p = 0; p < 8; p++) {
            const uint64_t Bv = *(const uint64_t*)&Bsh[k * NST + 2 * p];
            h2[p] = fma2_(abar2[p], h2[p], mul2_(xx2, Bv));
        }
    }

    uint64_t* hp = (uint64_t*)(g_hend + ((((size_t)(b * TCH + c)) * DINNER + d) << 4));
#pragma unroll
    for (int p = 0; p < 8; p++) hp[p] = h2[p];
}

// ---------------- scan pass 2: cross-chunk scan (2 states/thread, f32x2) --------
__global__ __launch_bounds__(256) void scan_pass2(const float* __restrict__ A_log)
{
    const int gid = blockIdx.x * 256 + threadIdx.x;   // over BATCH*DINNER*8
    const int p = gid & 7;
    const int d = (gid >> 3) & (DINNER - 1);
    const int b = gid >> 14;

    const float a0 = expf(-expf(A_log[d * NST + 2 * p])     * 0.1f * (float)LC);
    const float a1 = expf(-expf(A_log[d * NST + 2 * p + 1]) * 0.1f * (float)LC);
    const uint64_t ap2 = pk2(a0, a1);

    uint64_t H = 0ull;
#pragma unroll 8
    for (int c = 0; c < TCH; c++) {
        const size_t idx = ((((size_t)(b * TCH + c)) * DINNER + d) << 4) + 2 * p;
        *(uint64_t*)(g_Hst + idx) = H;
        H = fma2_(ap2, H, *(const uint64_t*)(g_hend + idx));
    }
}

// ---------------- scan pass 3: local scan + y + D*x + gate (f32x2 math) --------
__global__ __launch_bounds__(256) void scan_pass3(const float* __restrict__ A_log,
                                                  const float* __restrict__ Dvec)
{
    const int tid = threadIdx.x;
    const int d = blockIdx.x * 256 + tid;
    const int c = blockIdx.y;
    const int b = blockIdx.z;

    __shared__ float Bsh[LC * NST];
    __shared__ float Csh[LC * NST];
    {
        const size_t base = (size_t)(b * SEQL + c * LC) * NST;
        ((float4*)Bsh)[tid] = ((const float4*)(g_B + base))[tid];
        ((float4*)Csh)[tid] = ((const float4*)(g_C + base))[tid];
    }

    uint64_t abar2[8];
#pragma unroll
    for (int p = 0; p < 8; p++) {
        const float a0 = expf(-expf(A_log[d * NST + 2 * p])     * 0.1f);
        const float a1 = expf(-expf(A_log[d * NST + 2 * p + 1]) * 0.1f);
        abar2[p] = pk2(a0, a1);
    }
    const float Dd = Dvec[d];

    uint64_t h2[8];
    {
        const uint64_t* Hp = (const uint64_t*)(g_Hst + ((((size_t)(b * TCH + c)) * DINNER + d) << 4));
#pragma unroll
        for (int p = 0; p < 8; p++) h2[p] = Hp[p];
    }

    __syncthreads();

    const size_t off = (size_t)(b * SEQL + c * LC) * DINNER + d;
    const __half* xp = g_xc16 + off;
    const __half* gp = g_gateh + off;
    __half* yp = g_ya + off;

#pragma unroll 4
    for (int k = 0; k < LC; k++) {
        const float x = __half2float(xp[(size_t)k * DINNER]);
        const uint64_t xx2 = pk2(x, x);
        uint64_t acc2 = 0ull;
#pragma unroll
        for (int p = 0; p < 8; p++) {
            const uint64_t Bv = *(const uint64_t*)&Bsh[k * NST + 2 * p];
            h2[p] = fma2_(abar2[p], h2[p], mul2_(xx2, Bv));
            const uint64_t Cv = *(const uint64_t*)&Csh[k * NST + 2 * p];
            acc2 = fma2_(Cv, h2[p], acc2);
        }
        float alo, ahi; upk2(acc2, alo, ahi);
        const float y = (alo + ahi + Dd * x) * __half2float(gp[(size_t)k * DINNER]);
        yp[(size_t)k * DINNER] = __float2half_rn(y);
    }
}

// ---------------- launch ---------------------------------------------------------
extern "C" void kernel_launch(void* const* d_in, const int* in_sizes, int n_in,
                              void* d_out, int out_size)
{
    const float* x      = (const float*)d_in[0];
    const float* B_mod  = (const float*)d_in[1];
    const float* C_mod  = (const float*)d_in[2];
    const float* W_in   = (const float*)d_in[3];
    const float* b_in   = (const float*)d_in[4];
    const float* conv_w = (const float*)d_in[5];
    const float* conv_b = (const float*)d_in[6];
    const float* A_log  = (const float*)d_in[7];
    const float* Dv     = (const float*)d_in[8];
    const float* W_B    = (const float*)d_in[9];
    const float* b_B    = (const float*)d_in[10];
    const float* W_C    = (const float*)d_in[11];
    const float* b_C    = (const float*)d_in[12];
    const float* W_out  = (const float*)d_in[13];
    const float* b_out  = (const float*)d_in[14];
    float* out = (float*)d_out;

    cudaFuncSetAttribute(hgemm<0, 4096, 1024>,
                         cudaFuncAttributeMaxDynamicSharedMemorySize, GSMEM);
    cudaFuncSetAttribute(hgemm<1, 1024, 2048>,
                         cudaFuncAttributeMaxDynamicSharedMemorySize, GSMEM);
    cudaFuncSetAttribute(bc_hmma,
                         cudaFuncAttributeMaxDynamicSharedMemorySize, BC_SMEM);

    // 0) fused prep (convert x, transpose W_in/W_out/W_BC, init g_B/g_C biases)
    prep<<<14912, 256>>>(x, W_in, W_out, W_B, W_C, b_B, B_mod, b_C, C_mod);

    // 1) in_proj (HMMA fp16) + split + silu (x half fp32, gate fp16)
    hgemm<0, 4096, 1024><<<dim3(4096 / 128, MTOT / 128), 256, GSMEM>>>(b_in, nullptr);

    // 2) depthwise conv fp32->fp16, then B/C projections (HMMA)
    conv16<<<(MTOT * DINNER / 2) / 256, 256>>>(conv_w, conv_b);
    bc_hmma<<<dim3(MTOT / 128, 4), 256, BC_SMEM>>>();

    // 3) chunked scan (f32x2 packed state math; pass2 = 2 states/thread)
    scan_pass1<<<dim3(DINNER / 256, TCH, BATCH), 256>>>(A_log);
    scan_pass2<<<(BATCH * DINNER * 8) / 256, 256>>>(A_log);
    scan_pass3<<<dim3(DINNER / 256, TCH, BATCH), 256>>>(A_log, Dv);

    // 4) out_proj (HMMA fp16)
    hgemm<1, 1024, 2048><<<dim3(1024 / 128, MTOT / 128), 256, GSMEM>>>(b_out, out);
}